// round 7
// baseline (speedup 1.0000x reference)
#include <cuda_runtime.h>
#include <cstdint>
#include <cstddef>

// ---------------------------------------------------------------------------
// out[8192,4096] = x[8192,4096] @ W^T + b,  W = mu + exp(log_sigma)*eps
// tf32 mma.sync, warp-specialized. R7: dual producer warps (A/B split) +
// next-stage FULL wait hoisted above the final MMA blocks.
// ---------------------------------------------------------------------------
#define NROWS 8192
#define KDIM  4096
#define ODIM  4096

#define TILE_M 128
#define TILE_N 128
#define TILE_K 32
#define STAGES 3
#define K_ITERS (KDIM / TILE_K)            // 128

#define A_BYTES (TILE_M * TILE_K * 4)      // 16384
#define B_BYTES (TILE_N * TILE_K * 4)      // 16384
#define STAGE_BYTES (A_BYTES + B_BYTES)    // 32768
#define OFF_BAR   (STAGES * STAGE_BYTES)   // 98304
#define SMEM_TOTAL (OFF_BAR + 64)

__device__ float g_X[(size_t)NROWS * KDIM];
__device__ float g_W[(size_t)ODIM * KDIM];
__device__ float g_B[ODIM];

// ---------------------------------------------------------------------------
__device__ __forceinline__ uint32_t smem_u32(const void* p) {
    uint32_t a;
    asm("{ .reg .u64 t; cvta.to.shared.u64 t, %1; cvt.u32.u64 %0, t; }"
        : "=r"(a) : "l"(p));
    return a;
}
__device__ __forceinline__ void cp16(uint32_t smem_dst, const void* gptr) {
    asm volatile("cp.async.cg.shared.global [%0], [%1], 16;"
                 :: "r"(smem_dst), "l"(gptr) : "memory");
}
__device__ __forceinline__ void cp_async_arrive(uint32_t mbar) {
    asm volatile("cp.async.mbarrier.arrive.noinc.shared.b64 [%0];"
                 :: "r"(mbar) : "memory");
}
#define MBARRIER_INIT(addr, cnt) \
    asm volatile("mbarrier.init.shared.b64 [%0], %1;" :: "r"(addr), "r"(cnt) : "memory")
#define MBARRIER_ARRIVE(addr) \
    asm volatile("mbarrier.arrive.shared.b64 _, [%0];" :: "r"(addr) : "memory")

__device__ __forceinline__ void mbar_wait(uint32_t mbar, uint32_t parity) {
    uint32_t done;
    asm volatile(
        "{ .reg .pred p; mbarrier.try_wait.parity.acquire.cta.shared::cta.b64 p, [%1], %2;"
        " selp.b32 %0, 1, 0, p; }"
        : "=r"(done) : "r"(mbar), "r"(parity) : "memory");
    if (!done) {
        asm volatile(
            "{ .reg .pred P1;\n"
            "WAIT_LOOP_%=:\n"
            " mbarrier.try_wait.parity.acquire.cta.shared::cta.b64 P1, [%0], %1, 0x989680;\n"
            " @P1 bra.uni WAIT_DONE_%=;\n"
            " bra.uni WAIT_LOOP_%=;\n"
            "WAIT_DONE_%=:\n}"
            :: "r"(mbar), "r"(parity) : "memory");
    }
}

__device__ __forceinline__ uint32_t f2tf32(float x) {
    uint32_t o;
    asm("cvt.rna.tf32.f32 %0, %1;" : "=r"(o) : "f"(x));
    return o;
}
__device__ __forceinline__ void ldsm_x4(uint32_t* r, uint32_t addr) {
    asm volatile("ldmatrix.sync.aligned.m8n8.x4.shared.b16 {%0,%1,%2,%3}, [%4];"
                 : "=r"(r[0]), "=r"(r[1]), "=r"(r[2]), "=r"(r[3]) : "r"(addr));
}
__device__ __forceinline__ void mma_tf32(float* c, const uint32_t* a,
                                         uint32_t b0, uint32_t b1) {
    asm volatile(
        "mma.sync.aligned.m16n8k8.row.col.f32.tf32.tf32.f32 "
        "{%0,%1,%2,%3}, {%4,%5,%6,%7}, {%8,%9}, {%0,%1,%2,%3};"
        : "+f"(c[0]), "+f"(c[1]), "+f"(c[2]), "+f"(c[3])
        : "r"(a[0]), "r"(a[1]), "r"(a[2]), "r"(a[3]), "r"(b0), "r"(b1));
}

// ---------------------------------------------------------------------------
// Prep kernels
// ---------------------------------------------------------------------------
__global__ void prep_x_kernel(const float4* __restrict__ x) {
    size_t i = (size_t)blockIdx.x * blockDim.x + threadIdx.x;
    float4 v = x[i];
    float4 o;
    o.x = __uint_as_float(f2tf32(v.x));
    o.y = __uint_as_float(f2tf32(v.y));
    o.z = __uint_as_float(f2tf32(v.z));
    o.w = __uint_as_float(f2tf32(v.w));
    reinterpret_cast<float4*>(g_X)[i] = o;
}
__global__ void prep_w_kernel(const float4* __restrict__ mu,
                              const float4* __restrict__ ls,
                              const float4* __restrict__ eps) {
    size_t i = (size_t)blockIdx.x * blockDim.x + threadIdx.x;
    float4 m = mu[i], l = ls[i], e = eps[i];
    float4 o;
    o.x = __uint_as_float(f2tf32(m.x + expf(l.x) * e.x));
    o.y = __uint_as_float(f2tf32(m.y + expf(l.y) * e.y));
    o.z = __uint_as_float(f2tf32(m.z + expf(l.z) * e.z));
    o.w = __uint_as_float(f2tf32(m.w + expf(l.w) * e.w));
    reinterpret_cast<float4*>(g_W)[i] = o;
}
__global__ void prep_bias_kernel(const float* __restrict__ mub,
                                 const float* __restrict__ lsb,
                                 const float* __restrict__ epsb) {
    int i = blockIdx.x * blockDim.x + threadIdx.x;
    if (i < ODIM) g_B[i] = mub[i] + expf(lsb[i]) * epsb[i];
}

// ---------------------------------------------------------------------------
// GEMM: 2048 CTAs (64 m x 32 n, n fastest), 192 threads:
// warps 0-3 consumers (64x64, 2x2), warp 4 produces A, warp 5 produces B.
// full[s]: 64 cp-arrivals (2 producer warps); empty[s]: 128 consumer arrivals.
// ---------------------------------------------------------------------------
__global__ void __launch_bounds__(192, 2)
rand_linear_gemm_kernel(float* __restrict__ out) {
    extern __shared__ char smem[];
    const uint32_t sb = smem_u32(smem);
    const int tid = threadIdx.x;
    const int lane = tid & 31;
    const int wid = tid >> 5;

    const int m_tile = blockIdx.x >> 5;
    const int n_tile = blockIdx.x & 31;    // fast-varying: W stays L2-hot
    const int m0 = m_tile * TILE_M;
    const int n0 = n_tile * TILE_N;

    #define FULL_BAR(s)  (sb + OFF_BAR + (s) * 16)
    #define EMPTY_BAR(s) (sb + OFF_BAR + (s) * 16 + 8)

    if (tid == 0) {
        #pragma unroll
        for (int s = 0; s < STAGES; ++s) {
            MBARRIER_INIT(FULL_BAR(s), 64u);    // 2 producer warps x 32 lanes
            MBARRIER_INIT(EMPTY_BAR(s), 128u);  // consumer thread arrivals
        }
    }
    __syncthreads();   // only CTA-wide sync

    if (wid >= 4) {
        // ---------------- producer warps: wid4 -> A, wid5 -> B ----------------
        const int r0 = lane >> 3;          // 0..3
        const int tc = lane & 7;           // 16B chunk in 128B row
        const float* gSrc = (wid == 4)
            ? g_X + (size_t)(m0 + r0) * KDIM + tc * 4
            : g_W + (size_t)(n0 + r0) * KDIM + tc * 4;
        const uint32_t tileOff = (wid == 4) ? 0u : (uint32_t)A_BYTES;
        const uint32_t sw0 = (uint32_t)r0 * 128u + (uint32_t)((tc ^ (r0 & 7)) << 4);
        const uint32_t sw1 = (uint32_t)(r0 + 4) * 128u +
                             (uint32_t)((tc ^ ((r0 + 4) & 7)) << 4);

        int slot = 0, phase = 1;
        for (int it = 0; it < K_ITERS; ++it) {
            mbar_wait(EMPTY_BAR(slot), phase);
            const uint32_t tS = sb + slot * STAGE_BYTES + tileOff;
            const float* g = gSrc + it * TILE_K;
            #pragma unroll
            for (int j = 0; j < 16; ++j) {
                cp16(tS + sw0 + j * 1024u, g + (size_t)(8 * j) * KDIM);
                cp16(tS + sw1 + j * 1024u, g + (size_t)(8 * j + 4) * KDIM);
            }
            cp_async_arrive(FULL_BAR(slot));
            if (++slot == STAGES) { slot = 0; phase ^= 1; }
        }
        return;
    }

    // --------------------------- consumer warps ---------------------------
    const int wm0 = (wid & 1) * 64;
    const int wn0 = (wid >> 1) * 64;

    const int la15 = lane & 15;
    const uint32_t hi = (uint32_t)(lane >> 4);
    uint32_t aRow[4], aX7[4], bRow[4], bX7[4];
    #pragma unroll
    for (int i = 0; i < 4; ++i) {
        const uint32_t ra = (uint32_t)(wm0 + i * 16 + la15);
        aRow[i] = ra * 128u; aX7[i] = ra & 7u;
        const uint32_t rb = (uint32_t)(wn0 + i * 16 + la15);
        bRow[i] = rb * 128u; bX7[i] = rb & 7u;
    }

    float acc[4][8][4];
    #pragma unroll
    for (int i = 0; i < 4; ++i)
        #pragma unroll
        for (int j = 0; j < 8; ++j)
            #pragma unroll
            for (int r = 0; r < 4; ++r) acc[i][j][r] = 0.f;

    uint32_t a[2][4][4], b[2][4][4];

    #define LOAD_FRAGS(kk, buf, aB_, bB_)                                     \
        do {                                                                  \
            const uint32_t kc2 = (uint32_t)((kk) * 2) + hi;                   \
            _Pragma("unroll")                                                 \
            for (int i_ = 0; i_ < 4; ++i_)                                    \
                ldsm_x4(a[buf][i_], (aB_) + aRow[i_] + ((kc2 ^ aX7[i_]) << 4)); \
            _Pragma("unroll")                                                 \
            for (int j_ = 0; j_ < 4; ++j_)                                    \
                ldsm_x4(b[buf][j_], (bB_) + bRow[j_] + ((kc2 ^ bX7[j_]) << 4)); \
        } while (0)

    #define MMA_BLOCK(buf)                                                    \
        do {                                                                  \
            _Pragma("unroll")                                                 \
            for (int i_ = 0; i_ < 4; ++i_) {                                  \
                _Pragma("unroll")                                             \
                for (int j_ = 0; j_ < 4; ++j_) {                              \
                    mma_tf32(acc[i_][2 * j_ + 0], a[buf][i_], b[buf][j_][0],  \
                             b[buf][j_][2]);                                  \
                    mma_tf32(acc[i_][2 * j_ + 1], a[buf][i_], b[buf][j_][1],  \
                             b[buf][j_][3]);                                  \
                }                                                             \
            }                                                                 \
        } while (0)

    int slot = 0, phase = 0;
    mbar_wait(FULL_BAR(0), 0);
    for (int it = 0; it < K_ITERS; ++it) {
        const uint32_t aB = sb + slot * STAGE_BYTES;
        const uint32_t bB = aB + A_BYTES;

        LOAD_FRAGS(0, 0, aB, bB);
        LOAD_FRAGS(1, 1, aB, bB);
        MMA_BLOCK(0);                      // kk0
        LOAD_FRAGS(2, 0, aB, bB);
        MMA_BLOCK(1);                      // kk1
        LOAD_FRAGS(3, 1, aB, bB);
        MBARRIER_ARRIVE(EMPTY_BAR(slot));  // all reads of this stage issued

        int nslot = slot + 1, nphase = phase;
        if (nslot == STAGES) { nslot = 0; nphase ^= 1; }
        // Hoisted wait: tensor pipe drains kk2+kk3 below while we wait here.
        if (it + 1 < K_ITERS) mbar_wait(FULL_BAR(nslot), nphase);

        MMA_BLOCK(0);                      // kk2
        MMA_BLOCK(1);                      // kk3
        slot = nslot; phase = nphase;
    }

    // ---- epilogue: fused bias ----
    const int gid = lane >> 2;
    const int kc = lane & 3;
    #pragma unroll
    for (int j = 0; j < 8; ++j) {
        const int col = n0 + wn0 + j * 8 + kc * 2;
        float2 bv;
        bv.x = __ldg(&g_B[col]);
        bv.y = __ldg(&g_B[col + 1]);
        #pragma unroll
        for (int i = 0; i < 4; ++i) {
            const int row = m0 + wm0 + i * 16 + gid;
            float2 v0 = make_float2(acc[i][j][0] + bv.x, acc[i][j][1] + bv.y);
            float2 v1 = make_float2(acc[i][j][2] + bv.x, acc[i][j][3] + bv.y);
            *reinterpret_cast<float2*>(out + (size_t)row * ODIM + col) = v0;
            *reinterpret_cast<float2*>(out + (size_t)(row + 8) * ODIM + col) = v1;
        }
    }
}

// ---------------------------------------------------------------------------
extern "C" void kernel_launch(void* const* d_in, const int* in_sizes, int n_in,
                              void* d_out, int out_size) {
    const float* x    = (const float*)d_in[0];
    const float* muw  = (const float*)d_in[1];
    const float* lsw  = (const float*)d_in[2];
    const float* mub  = (const float*)d_in[3];
    const float* lsb  = (const float*)d_in[4];
    const float* epsw = (const float*)d_in[5];
    const float* epsb = (const float*)d_in[6];
    float* out = (float*)d_out;

    cudaFuncSetAttribute(rand_linear_gemm_kernel,
                         cudaFuncAttributeMaxDynamicSharedMemorySize, SMEM_TOTAL);

    prep_x_kernel<<<32768, 256>>>((const float4*)x);
    prep_w_kernel<<<16384, 256>>>((const float4*)muw, (const float4*)lsw,
                                  (const float4*)epsw);
    prep_bias_kernel<<<16, 256>>>(mub, lsb, epsb);

    rand_linear_gemm_kernel<<<(NROWS / TILE_M) * (ODIM / TILE_N), 192,
                              SMEM_TOTAL>>>(out);
}

// round 8
// speedup vs baseline: 1.6395x; 1.6395x over previous
#include <cuda_runtime.h>
#include <cstdint>
#include <cstddef>

// ---------------------------------------------------------------------------
// out[8192,4096] = x[8192,4096] @ W^T + b,  W = mu + exp(log_sigma)*eps
// tf32 mma.sync, warp-specialized (R6 base: single producer warp).
// R8 single change: next-stage FULL wait hoisted between the two tail MMA
// blocks so queued tensor work covers the try_wait fast path.
// ---------------------------------------------------------------------------
#define NROWS 8192
#define KDIM  4096
#define ODIM  4096

#define TILE_M 128
#define TILE_N 128
#define TILE_K 32
#define STAGES 3
#define K_ITERS (KDIM / TILE_K)            // 128

#define A_BYTES (TILE_M * TILE_K * 4)      // 16384
#define B_BYTES (TILE_N * TILE_K * 4)      // 16384
#define STAGE_BYTES (A_BYTES + B_BYTES)    // 32768
#define OFF_BAR   (STAGES * STAGE_BYTES)   // 98304
#define SMEM_TOTAL (OFF_BAR + 64)

__device__ float g_X[(size_t)NROWS * KDIM];
__device__ float g_W[(size_t)ODIM * KDIM];
__device__ float g_B[ODIM];

// ---------------------------------------------------------------------------
__device__ __forceinline__ uint32_t smem_u32(const void* p) {
    uint32_t a;
    asm("{ .reg .u64 t; cvta.to.shared.u64 t, %1; cvt.u32.u64 %0, t; }"
        : "=r"(a) : "l"(p));
    return a;
}
__device__ __forceinline__ void cp16(uint32_t smem_dst, const void* gptr) {
    asm volatile("cp.async.cg.shared.global [%0], [%1], 16;"
                 :: "r"(smem_dst), "l"(gptr) : "memory");
}
__device__ __forceinline__ void cp_async_arrive(uint32_t mbar) {
    asm volatile("cp.async.mbarrier.arrive.noinc.shared.b64 [%0];"
                 :: "r"(mbar) : "memory");
}
#define MBARRIER_INIT(addr, cnt) \
    asm volatile("mbarrier.init.shared.b64 [%0], %1;" :: "r"(addr), "r"(cnt) : "memory")
#define MBARRIER_ARRIVE(addr) \
    asm volatile("mbarrier.arrive.shared.b64 _, [%0];" :: "r"(addr) : "memory")

__device__ __forceinline__ void mbar_wait(uint32_t mbar, uint32_t parity) {
    uint32_t done;
    asm volatile(
        "{ .reg .pred p; mbarrier.try_wait.parity.acquire.cta.shared::cta.b64 p, [%1], %2;"
        " selp.b32 %0, 1, 0, p; }"
        : "=r"(done) : "r"(mbar), "r"(parity) : "memory");
    if (!done) {
        asm volatile(
            "{ .reg .pred P1;\n"
            "WAIT_LOOP_%=:\n"
            " mbarrier.try_wait.parity.acquire.cta.shared::cta.b64 P1, [%0], %1, 0x989680;\n"
            " @P1 bra.uni WAIT_DONE_%=;\n"
            " bra.uni WAIT_LOOP_%=;\n"
            "WAIT_DONE_%=:\n}"
            :: "r"(mbar), "r"(parity) : "memory");
    }
}

__device__ __forceinline__ uint32_t f2tf32(float x) {
    uint32_t o;
    asm("cvt.rna.tf32.f32 %0, %1;" : "=r"(o) : "f"(x));
    return o;
}
__device__ __forceinline__ void ldsm_x4(uint32_t* r, uint32_t addr) {
    asm volatile("ldmatrix.sync.aligned.m8n8.x4.shared.b16 {%0,%1,%2,%3}, [%4];"
                 : "=r"(r[0]), "=r"(r[1]), "=r"(r[2]), "=r"(r[3]) : "r"(addr));
}
__device__ __forceinline__ void mma_tf32(float* c, const uint32_t* a,
                                         uint32_t b0, uint32_t b1) {
    asm volatile(
        "mma.sync.aligned.m16n8k8.row.col.f32.tf32.tf32.f32 "
        "{%0,%1,%2,%3}, {%4,%5,%6,%7}, {%8,%9}, {%0,%1,%2,%3};"
        : "+f"(c[0]), "+f"(c[1]), "+f"(c[2]), "+f"(c[3])
        : "r"(a[0]), "r"(a[1]), "r"(a[2]), "r"(a[3]), "r"(b0), "r"(b1));
}

// ---------------------------------------------------------------------------
// Prep kernels
// ---------------------------------------------------------------------------
__global__ void prep_x_kernel(const float4* __restrict__ x) {
    size_t i = (size_t)blockIdx.x * blockDim.x + threadIdx.x;
    float4 v = x[i];
    float4 o;
    o.x = __uint_as_float(f2tf32(v.x));
    o.y = __uint_as_float(f2tf32(v.y));
    o.z = __uint_as_float(f2tf32(v.z));
    o.w = __uint_as_float(f2tf32(v.w));
    reinterpret_cast<float4*>(g_X)[i] = o;
}
__global__ void prep_w_kernel(const float4* __restrict__ mu,
                              const float4* __restrict__ ls,
                              const float4* __restrict__ eps) {
    size_t i = (size_t)blockIdx.x * blockDim.x + threadIdx.x;
    float4 m = mu[i], l = ls[i], e = eps[i];
    float4 o;
    o.x = __uint_as_float(f2tf32(m.x + expf(l.x) * e.x));
    o.y = __uint_as_float(f2tf32(m.y + expf(l.y) * e.y));
    o.z = __uint_as_float(f2tf32(m.z + expf(l.z) * e.z));
    o.w = __uint_as_float(f2tf32(m.w + expf(l.w) * e.w));
    reinterpret_cast<float4*>(g_W)[i] = o;
}
__global__ void prep_bias_kernel(const float* __restrict__ mub,
                                 const float* __restrict__ lsb,
                                 const float* __restrict__ epsb) {
    int i = blockIdx.x * blockDim.x + threadIdx.x;
    if (i < ODIM) g_B[i] = mub[i] + expf(lsb[i]) * epsb[i];
}

// ---------------------------------------------------------------------------
// GEMM: 2048 CTAs (64 m x 32 n, n fastest), 160 threads:
// warps 0-3 consumers (64x64 tiles, 2x2), warp 4 producer (all cp.async).
// full[s]: 32 cp-arrivals; empty[s]: 128 consumer arrivals.
// ---------------------------------------------------------------------------
__global__ void __launch_bounds__(160, 2)
rand_linear_gemm_kernel(float* __restrict__ out) {
    extern __shared__ char smem[];
    const uint32_t sb = smem_u32(smem);
    const int tid = threadIdx.x;
    const int lane = tid & 31;
    const int wid = tid >> 5;

    const int m_tile = blockIdx.x >> 5;
    const int n_tile = blockIdx.x & 31;    // fast-varying: W stays L2-hot
    const int m0 = m_tile * TILE_M;
    const int n0 = n_tile * TILE_N;

    #define FULL_BAR(s)  (sb + OFF_BAR + (s) * 16)
    #define EMPTY_BAR(s) (sb + OFF_BAR + (s) * 16 + 8)

    if (tid == 0) {
        #pragma unroll
        for (int s = 0; s < STAGES; ++s) {
            MBARRIER_INIT(FULL_BAR(s), 32u);    // producer warp cp-arrivals
            MBARRIER_INIT(EMPTY_BAR(s), 128u);  // consumer thread arrivals
        }
    }
    __syncthreads();   // only CTA-wide sync in the kernel

    if (wid == 4) {
        // ------------------------- producer warp -------------------------
        const int r0 = lane >> 3;          // 0..3
        const int tc = lane & 7;           // 16B chunk in 128B row
        const float* gA = g_X + (size_t)(m0 + r0) * KDIM + tc * 4;
        const float* gB = g_W + (size_t)(n0 + r0) * KDIM + tc * 4;
        const uint32_t sw0 = (uint32_t)r0 * 128u + (uint32_t)((tc ^ (r0 & 7)) << 4);
        const uint32_t sw1 = (uint32_t)(r0 + 4) * 128u +
                             (uint32_t)((tc ^ ((r0 + 4) & 7)) << 4);

        int slot = 0, phase = 1;
        for (int it = 0; it < K_ITERS; ++it) {
            mbar_wait(EMPTY_BAR(slot), phase);
            const uint32_t aS = sb + slot * STAGE_BYTES;
            const uint32_t bS = aS + A_BYTES;
            const float* ga = gA + it * TILE_K;
            const float* gb = gB + it * TILE_K;
            #pragma unroll
            for (int j = 0; j < 16; ++j) {   // A: rows r0+8j, r0+4+8j
                cp16(aS + sw0 + j * 1024u, ga + (size_t)(8 * j) * KDIM);
                cp16(aS + sw1 + j * 1024u, ga + (size_t)(8 * j + 4) * KDIM);
            }
            #pragma unroll
            for (int j = 0; j < 16; ++j) {   // B
                cp16(bS + sw0 + j * 1024u, gb + (size_t)(8 * j) * KDIM);
                cp16(bS + sw1 + j * 1024u, gb + (size_t)(8 * j + 4) * KDIM);
            }
            cp_async_arrive(FULL_BAR(slot));
            if (++slot == STAGES) { slot = 0; phase ^= 1; }
        }
        return;
    }

    // --------------------------- consumer warps ---------------------------
    const int wm0 = (wid & 1) * 64;
    const int wn0 = (wid >> 1) * 64;

    const int la15 = lane & 15;
    const uint32_t hi = (uint32_t)(lane >> 4);
    uint32_t aRow[4], aX7[4], bRow[4], bX7[4];
    #pragma unroll
    for (int i = 0; i < 4; ++i) {
        const uint32_t ra = (uint32_t)(wm0 + i * 16 + la15);
        aRow[i] = ra * 128u; aX7[i] = ra & 7u;
        const uint32_t rb = (uint32_t)(wn0 + i * 16 + la15);
        bRow[i] = rb * 128u; bX7[i] = rb & 7u;
    }

    float acc[4][8][4];
    #pragma unroll
    for (int i = 0; i < 4; ++i)
        #pragma unroll
        for (int j = 0; j < 8; ++j)
            #pragma unroll
            for (int r = 0; r < 4; ++r) acc[i][j][r] = 0.f;

    uint32_t a[2][4][4], b[2][4][4];

    #define LOAD_FRAGS(kk, buf, aB_, bB_)                                     \
        do {                                                                  \
            const uint32_t kc2 = (uint32_t)((kk) * 2) + hi;                   \
            _Pragma("unroll")                                                 \
            for (int i_ = 0; i_ < 4; ++i_)                                    \
                ldsm_x4(a[buf][i_], (aB_) + aRow[i_] + ((kc2 ^ aX7[i_]) << 4)); \
            _Pragma("unroll")                                                 \
            for (int j_ = 0; j_ < 4; ++j_)                                    \
                ldsm_x4(b[buf][j_], (bB_) + bRow[j_] + ((kc2 ^ bX7[j_]) << 4)); \
        } while (0)

    #define MMA_BLOCK(buf)                                                    \
        do {                                                                  \
            _Pragma("unroll")                                                 \
            for (int i_ = 0; i_ < 4; ++i_) {                                  \
                _Pragma("unroll")                                             \
                for (int j_ = 0; j_ < 4; ++j_) {                              \
                    mma_tf32(acc[i_][2 * j_ + 0], a[buf][i_], b[buf][j_][0],  \
                             b[buf][j_][2]);                                  \
                    mma_tf32(acc[i_][2 * j_ + 1], a[buf][i_], b[buf][j_][1],  \
                             b[buf][j_][3]);                                  \
                }                                                             \
            }                                                                 \
        } while (0)

    int slot = 0, phase = 0;
    mbar_wait(FULL_BAR(0), 0);             // stage 0 ready
    for (int it = 0; it < K_ITERS; ++it) {
        const uint32_t aB = sb + slot * STAGE_BYTES;
        const uint32_t bB = aB + A_BYTES;

        LOAD_FRAGS(0, 0, aB, bB);
        LOAD_FRAGS(1, 1, aB, bB);
        MMA_BLOCK(0);                      // kk0
        LOAD_FRAGS(2, 0, aB, bB);
        MMA_BLOCK(1);                      // kk1
        LOAD_FRAGS(3, 1, aB, bB);
        MBARRIER_ARRIVE(EMPTY_BAR(slot));  // all reads of this stage issued
        MMA_BLOCK(0);                      // kk2 (also covers wait below)

        int nslot = slot + 1, nphase = phase;
        if (nslot == STAGES) { nslot = 0; nphase ^= 1; }
        // R8 single change: wait here (one MMA block still queued) instead of
        // at the top of the next iteration with an empty tensor pipe.
        if (it + 1 < K_ITERS) mbar_wait(FULL_BAR(nslot), nphase);

        MMA_BLOCK(1);                      // kk3
        slot = nslot; phase = nphase;
    }

    // ---- epilogue: fused bias ----
    const int gid = lane >> 2;
    const int kc = lane & 3;
    #pragma unroll
    for (int j = 0; j < 8; ++j) {
        const int col = n0 + wn0 + j * 8 + kc * 2;
        float2 bv;
        bv.x = __ldg(&g_B[col]);
        bv.y = __ldg(&g_B[col + 1]);
        #pragma unroll
        for (int i = 0; i < 4; ++i) {
            const int row = m0 + wm0 + i * 16 + gid;
            float2 v0 = make_float2(acc[i][j][0] + bv.x, acc[i][j][1] + bv.y);
            float2 v1 = make_float2(acc[i][j][2] + bv.x, acc[i][j][3] + bv.y);
            *reinterpret_cast<float2*>(out + (size_t)row * ODIM + col) = v0;
            *reinterpret_cast<float2*>(out + (size_t)(row + 8) * ODIM + col) = v1;
        }
    }
}

// ---------------------------------------------------------------------------
extern "C" void kernel_launch(void* const* d_in, const int* in_sizes, int n_in,
                              void* d_out, int out_size) {
    const float* x    = (const float*)d_in[0];
    const float* muw  = (const float*)d_in[1];
    const float* lsw  = (const float*)d_in[2];
    const float* mub  = (const float*)d_in[3];
    const float* lsb  = (const float*)d_in[4];
    const float* epsw = (const float*)d_in[5];
    const float* epsb = (const float*)d_in[6];
    float* out = (float*)d_out;

    cudaFuncSetAttribute(rand_linear_gemm_kernel,
                         cudaFuncAttributeMaxDynamicSharedMemorySize, SMEM_TOTAL);

    prep_x_kernel<<<32768, 256>>>((const float4*)x);
    prep_w_kernel<<<16384, 256>>>((const float4*)muw, (const float4*)lsw,
                                  (const float4*)epsw);
    prep_bias_kernel<<<16, 256>>>(mub, lsb, epsb);

    rand_linear_gemm_kernel<<<(NROWS / TILE_M) * (ODIM / TILE_N), 160,
                              SMEM_TOTAL>>>(out);
}

// round 9
// speedup vs baseline: 1.9838x; 1.2100x over previous
#include <cuda_runtime.h>
#include <cstdint>
#include <cstddef>

// ---------------------------------------------------------------------------
// out[8192,4096] = x[8192,4096] @ W^T + b,  W = mu + exp(log_sigma)*eps
// tf32 mma.sync, warp-specialized. R9: CTA tile 256x128, 1 CTA/SM,
// 8 consumer warps (64x64) + 2 producer warps; R6 sync structure verbatim.
// ---------------------------------------------------------------------------
#define NROWS 8192
#define KDIM  4096
#define ODIM  4096

#define TILE_M 256
#define TILE_N 128
#define TILE_K 32
#define STAGES 3
#define K_ITERS (KDIM / TILE_K)            // 128

#define A_BYTES (TILE_M * TILE_K * 4)      // 32768
#define B_BYTES (TILE_N * TILE_K * 4)      // 16384
#define STAGE_BYTES (A_BYTES + B_BYTES)    // 49152
#define OFF_BAR   (STAGES * STAGE_BYTES)   // 147456
#define SMEM_TOTAL (OFF_BAR + 64)

__device__ float g_X[(size_t)NROWS * KDIM];
__device__ float g_W[(size_t)ODIM * KDIM];
__device__ float g_B[ODIM];

// ---------------------------------------------------------------------------
__device__ __forceinline__ uint32_t smem_u32(const void* p) {
    uint32_t a;
    asm("{ .reg .u64 t; cvta.to.shared.u64 t, %1; cvt.u32.u64 %0, t; }"
        : "=r"(a) : "l"(p));
    return a;
}
__device__ __forceinline__ void cp16(uint32_t smem_dst, const void* gptr) {
    asm volatile("cp.async.cg.shared.global [%0], [%1], 16;"
                 :: "r"(smem_dst), "l"(gptr) : "memory");
}
__device__ __forceinline__ void cp_async_arrive(uint32_t mbar) {
    asm volatile("cp.async.mbarrier.arrive.noinc.shared.b64 [%0];"
                 :: "r"(mbar) : "memory");
}
#define MBARRIER_INIT(addr, cnt) \
    asm volatile("mbarrier.init.shared.b64 [%0], %1;" :: "r"(addr), "r"(cnt) : "memory")
#define MBARRIER_ARRIVE(addr) \
    asm volatile("mbarrier.arrive.shared.b64 _, [%0];" :: "r"(addr) : "memory")

__device__ __forceinline__ void mbar_wait(uint32_t mbar, uint32_t parity) {
    uint32_t done;
    asm volatile(
        "{ .reg .pred p; mbarrier.try_wait.parity.acquire.cta.shared::cta.b64 p, [%1], %2;"
        " selp.b32 %0, 1, 0, p; }"
        : "=r"(done) : "r"(mbar), "r"(parity) : "memory");
    if (!done) {
        asm volatile(
            "{ .reg .pred P1;\n"
            "WAIT_LOOP_%=:\n"
            " mbarrier.try_wait.parity.acquire.cta.shared::cta.b64 P1, [%0], %1, 0x989680;\n"
            " @P1 bra.uni WAIT_DONE_%=;\n"
            " bra.uni WAIT_LOOP_%=;\n"
            "WAIT_DONE_%=:\n}"
            :: "r"(mbar), "r"(parity) : "memory");
    }
}

__device__ __forceinline__ uint32_t f2tf32(float x) {
    uint32_t o;
    asm("cvt.rna.tf32.f32 %0, %1;" : "=r"(o) : "f"(x));
    return o;
}
__device__ __forceinline__ void ldsm_x4(uint32_t* r, uint32_t addr) {
    asm volatile("ldmatrix.sync.aligned.m8n8.x4.shared.b16 {%0,%1,%2,%3}, [%4];"
                 : "=r"(r[0]), "=r"(r[1]), "=r"(r[2]), "=r"(r[3]) : "r"(addr));
}
__device__ __forceinline__ void mma_tf32(float* c, const uint32_t* a,
                                         uint32_t b0, uint32_t b1) {
    asm volatile(
        "mma.sync.aligned.m16n8k8.row.col.f32.tf32.tf32.f32 "
        "{%0,%1,%2,%3}, {%4,%5,%6,%7}, {%8,%9}, {%0,%1,%2,%3};"
        : "+f"(c[0]), "+f"(c[1]), "+f"(c[2]), "+f"(c[3])
        : "r"(a[0]), "r"(a[1]), "r"(a[2]), "r"(a[3]), "r"(b0), "r"(b1));
}

// ---------------------------------------------------------------------------
// Prep kernels
// ---------------------------------------------------------------------------
__global__ void prep_x_kernel(const float4* __restrict__ x) {
    size_t i = (size_t)blockIdx.x * blockDim.x + threadIdx.x;
    float4 v = x[i];
    float4 o;
    o.x = __uint_as_float(f2tf32(v.x));
    o.y = __uint_as_float(f2tf32(v.y));
    o.z = __uint_as_float(f2tf32(v.z));
    o.w = __uint_as_float(f2tf32(v.w));
    reinterpret_cast<float4*>(g_X)[i] = o;
}
__global__ void prep_w_kernel(const float4* __restrict__ mu,
                              const float4* __restrict__ ls,
                              const float4* __restrict__ eps) {
    size_t i = (size_t)blockIdx.x * blockDim.x + threadIdx.x;
    float4 m = mu[i], l = ls[i], e = eps[i];
    float4 o;
    o.x = __uint_as_float(f2tf32(m.x + expf(l.x) * e.x));
    o.y = __uint_as_float(f2tf32(m.y + expf(l.y) * e.y));
    o.z = __uint_as_float(f2tf32(m.z + expf(l.z) * e.z));
    o.w = __uint_as_float(f2tf32(m.w + expf(l.w) * e.w));
    reinterpret_cast<float4*>(g_W)[i] = o;
}
__global__ void prep_bias_kernel(const float* __restrict__ mub,
                                 const float* __restrict__ lsb,
                                 const float* __restrict__ epsb) {
    int i = blockIdx.x * blockDim.x + threadIdx.x;
    if (i < ODIM) g_B[i] = mub[i] + expf(lsb[i]) * epsb[i];
}

// ---------------------------------------------------------------------------
// GEMM: 1024 CTAs (32 m x 32 n, n fastest), 320 threads:
// warps 0-7 consumers (64x64 tiles in 4x2), warps 8-9 producers (A/B halves).
// full[s]: 64 cp-arrivals (2 warps); empty[s]: 256 consumer arrivals.
// ---------------------------------------------------------------------------
__global__ void __launch_bounds__(320, 1)
rand_linear_gemm_kernel(float* __restrict__ out) {
    extern __shared__ char smem[];
    const uint32_t sb = smem_u32(smem);
    const int tid = threadIdx.x;
    const int lane = tid & 31;
    const int wid = tid >> 5;

    const int m_tile = blockIdx.x >> 5;    // 32
    const int n_tile = blockIdx.x & 31;    // 32 (fast-varying: W stays L2-hot)
    const int m0 = m_tile * TILE_M;
    const int n0 = n_tile * TILE_N;

    #define FULL_BAR(s)  (sb + OFF_BAR + (s) * 16)
    #define EMPTY_BAR(s) (sb + OFF_BAR + (s) * 16 + 8)

    if (tid == 0) {
        #pragma unroll
        for (int s = 0; s < STAGES; ++s) {
            MBARRIER_INIT(FULL_BAR(s), 64u);    // 2 producer warps x 32 lanes
            MBARRIER_INIT(EMPTY_BAR(s), 256u);  // 8 consumer warps x 32 lanes
        }
    }
    __syncthreads();   // only CTA-wide sync

    if (wid >= 8) {
        // ------------- producer warps: each fills half of A and half of B ----
        const int ph = wid - 8;            // 0 or 1
        const int r0 = lane >> 3;          // 0..3
        const int tc = lane & 7;           // 16B chunk in 128B row
        // A half: rows [ph*128, ph*128+128); B half: rows [ph*64, ph*64+64)
        const float* gA = g_X + (size_t)(m0 + ph * 128 + r0) * KDIM + tc * 4;
        const float* gB = g_W + (size_t)(n0 + ph * 64 + r0) * KDIM + tc * 4;
        const uint32_t aOff = (uint32_t)(ph * 128) * 128u;   // smem row offset
        const uint32_t bOff = (uint32_t)(ph * 64) * 128u;
        const uint32_t sw0 = (uint32_t)r0 * 128u + (uint32_t)((tc ^ (r0 & 7)) << 4);
        const uint32_t sw1 = (uint32_t)(r0 + 4) * 128u +
                             (uint32_t)((tc ^ ((r0 + 4) & 7)) << 4);

        int slot = 0, phase = 1;
        for (int it = 0; it < K_ITERS; ++it) {
            mbar_wait(EMPTY_BAR(slot), phase);
            const uint32_t aS = sb + slot * STAGE_BYTES + aOff;
            const uint32_t bS = sb + slot * STAGE_BYTES + A_BYTES + bOff;
            const float* ga = gA + it * TILE_K;
            const float* gb = gB + it * TILE_K;
            #pragma unroll
            for (int j = 0; j < 16; ++j) {   // A half: 128 rows
                cp16(aS + sw0 + j * 1024u, ga + (size_t)(8 * j) * KDIM);
                cp16(aS + sw1 + j * 1024u, ga + (size_t)(8 * j + 4) * KDIM);
            }
            #pragma unroll
            for (int j = 0; j < 8; ++j) {    // B half: 64 rows
                cp16(bS + sw0 + j * 1024u, gb + (size_t)(8 * j) * KDIM);
                cp16(bS + sw1 + j * 1024u, gb + (size_t)(8 * j + 4) * KDIM);
            }
            cp_async_arrive(FULL_BAR(slot));
            if (++slot == STAGES) { slot = 0; phase ^= 1; }
        }
        return;
    }

    // --------------------------- consumer warps ---------------------------
    const int wm0 = (wid & 3) * 64;        // 0..192
    const int wn0 = (wid >> 2) * 64;       // 0 or 64

    const int la15 = lane & 15;
    const uint32_t hi = (uint32_t)(lane >> 4);
    uint32_t aRow[4], aX7[4], bRow[4], bX7[4];
    #pragma unroll
    for (int i = 0; i < 4; ++i) {
        const uint32_t ra = (uint32_t)(wm0 + i * 16 + la15);
        aRow[i] = ra * 128u; aX7[i] = ra & 7u;
        const uint32_t rb = (uint32_t)(wn0 + i * 16 + la15);
        bRow[i] = rb * 128u; bX7[i] = rb & 7u;
    }

    float acc[4][8][4];
    #pragma unroll
    for (int i = 0; i < 4; ++i)
        #pragma unroll
        for (int j = 0; j < 8; ++j)
            #pragma unroll
            for (int r = 0; r < 4; ++r) acc[i][j][r] = 0.f;

    uint32_t a[2][4][4], b[2][4][4];

    #define LOAD_FRAGS(kk, buf, aB_, bB_)                                     \
        do {                                                                  \
            const uint32_t kc2 = (uint32_t)((kk) * 2) + hi;                   \
            _Pragma("unroll")                                                 \
            for (int i_ = 0; i_ < 4; ++i_)                                    \
                ldsm_x4(a[buf][i_], (aB_) + aRow[i_] + ((kc2 ^ aX7[i_]) << 4)); \
            _Pragma("unroll")                                                 \
            for (int j_ = 0; j_ < 4; ++j_)                                    \
                ldsm_x4(b[buf][j_], (bB_) + bRow[j_] + ((kc2 ^ bX7[j_]) << 4)); \
        } while (0)

    #define MMA_BLOCK(buf)                                                    \
        do {                                                                  \
            _Pragma("unroll")                                                 \
            for (int i_ = 0; i_ < 4; ++i_) {                                  \
                _Pragma("unroll")                                             \
                for (int j_ = 0; j_ < 4; ++j_) {                              \
                    mma_tf32(acc[i_][2 * j_ + 0], a[buf][i_], b[buf][j_][0],  \
                             b[buf][j_][2]);                                  \
                    mma_tf32(acc[i_][2 * j_ + 1], a[buf][i_], b[buf][j_][1],  \
                             b[buf][j_][3]);                                  \
                }                                                             \
            }                                                                 \
        } while (0)

    int slot = 0, phase = 0;
    for (int it = 0; it < K_ITERS; ++it) {
        mbar_wait(FULL_BAR(slot), phase);   // R6 placement (loop top)
        const uint32_t aB = sb + slot * STAGE_BYTES;
        const uint32_t bB = aB + A_BYTES;

        LOAD_FRAGS(0, 0, aB, bB);
        LOAD_FRAGS(1, 1, aB, bB);
        MMA_BLOCK(0);                      // kk0
        LOAD_FRAGS(2, 0, aB, bB);
        MMA_BLOCK(1);                      // kk1
        LOAD_FRAGS(3, 1, aB, bB);
        MBARRIER_ARRIVE(EMPTY_BAR(slot));  // stage reads done — release early
        MMA_BLOCK(0);                      // kk2
        MMA_BLOCK(1);                      // kk3

        if (++slot == STAGES) { slot = 0; phase ^= 1; }
    }

    // ---- epilogue: fused bias ----
    const int gid = lane >> 2;
    const int kc = lane & 3;
    #pragma unroll
    for (int j = 0; j < 8; ++j) {
        const int col = n0 + wn0 + j * 8 + kc * 2;
        float2 bv;
        bv.x = __ldg(&g_B[col]);
        bv.y = __ldg(&g_B[col + 1]);
        #pragma unroll
        for (int i = 0; i < 4; ++i) {
            const int row = m0 + wm0 + i * 16 + gid;
            float2 v0 = make_float2(acc[i][j][0] + bv.x, acc[i][j][1] + bv.y);
            float2 v1 = make_float2(acc[i][j][2] + bv.x, acc[i][j][3] + bv.y);
            *reinterpret_cast<float2*>(out + (size_t)row * ODIM + col) = v0;
            *reinterpret_cast<float2*>(out + (size_t)(row + 8) * ODIM + col) = v1;
        }
    }
}

// ---------------------------------------------------------------------------
extern "C" void kernel_launch(void* const* d_in, const int* in_sizes, int n_in,
                              void* d_out, int out_size) {
    const float* x    = (const float*)d_in[0];
    const float* muw  = (const float*)d_in[1];
    const float* lsw  = (const float*)d_in[2];
    const float* mub  = (const float*)d_in[3];
    const float* lsb  = (const float*)d_in[4];
    const float* epsw = (const float*)d_in[5];
    const float* epsb = (const float*)d_in[6];
    float* out = (float*)d_out;

    cudaFuncSetAttribute(rand_linear_gemm_kernel,
                         cudaFuncAttributeMaxDynamicSharedMemorySize, SMEM_TOTAL);

    prep_x_kernel<<<32768, 256>>>((const float4*)x);
    prep_w_kernel<<<16384, 256>>>((const float4*)muw, (const float4*)lsw,
                                  (const float4*)epsw);
    prep_bias_kernel<<<16, 256>>>(mub, lsb, epsb);

    rand_linear_gemm_kernel<<<(NROWS / TILE_M) * (ODIM / TILE_N), 320,
                              SMEM_TOTAL>>>(out);
}

// round 10
// speedup vs baseline: 3.7428x; 1.8866x over previous
#include <cuda_runtime.h>
#include <cuda_fp16.h>
#include <cstdint>
#include <cstddef>

// ---------------------------------------------------------------------------
// out[8192,4096] = x[8192,4096] @ W^T + b,  W = mu + exp(log_sigma)*eps
// R10: fp16 m16n8k16 mma (11-bit mantissa == tf32, half the HMMA count).
// Structure = R9 (best known): 256x128 CTA tile, 1 CTA/SM, 8 consumer +
// 2 producer warps, 3-stage cp.async + mbarrier ring. TILE_K=64 fp16 keeps
// rows at 128B -> smem layout, swizzle, producer, ldmatrix all unchanged.
// ---------------------------------------------------------------------------
#define NROWS 8192
#define KDIM  4096
#define ODIM  4096

#define TILE_M 256
#define TILE_N 128
#define TILE_K 64                          // fp16: 64 halfs = 128 B/row
#define STAGES 3
#define K_ITERS (KDIM / TILE_K)            // 64

#define A_BYTES (TILE_M * TILE_K * 2)      // 32768
#define B_BYTES (TILE_N * TILE_K * 2)      // 16384
#define STAGE_BYTES (A_BYTES + B_BYTES)    // 49152
#define OFF_BAR   (STAGES * STAGE_BYTES)   // 147456
#define SMEM_TOTAL (OFF_BAR + 64)

__device__ __half g_X[(size_t)NROWS * KDIM];  // fp16 x
__device__ __half g_W[(size_t)ODIM * KDIM];   // fp16 sampled weight
__device__ float  g_B[ODIM];                  // fp32 sampled bias

// ---------------------------------------------------------------------------
__device__ __forceinline__ uint32_t smem_u32(const void* p) {
    uint32_t a;
    asm("{ .reg .u64 t; cvta.to.shared.u64 t, %1; cvt.u32.u64 %0, t; }"
        : "=r"(a) : "l"(p));
    return a;
}
__device__ __forceinline__ void cp16(uint32_t smem_dst, const void* gptr) {
    asm volatile("cp.async.cg.shared.global [%0], [%1], 16;"
                 :: "r"(smem_dst), "l"(gptr) : "memory");
}
__device__ __forceinline__ void cp_async_arrive(uint32_t mbar) {
    asm volatile("cp.async.mbarrier.arrive.noinc.shared.b64 [%0];"
                 :: "r"(mbar) : "memory");
}
#define MBARRIER_INIT(addr, cnt) \
    asm volatile("mbarrier.init.shared.b64 [%0], %1;" :: "r"(addr), "r"(cnt) : "memory")
#define MBARRIER_ARRIVE(addr) \
    asm volatile("mbarrier.arrive.shared.b64 _, [%0];" :: "r"(addr) : "memory")

__device__ __forceinline__ void mbar_wait(uint32_t mbar, uint32_t parity) {
    uint32_t done;
    asm volatile(
        "{ .reg .pred p; mbarrier.try_wait.parity.acquire.cta.shared::cta.b64 p, [%1], %2;"
        " selp.b32 %0, 1, 0, p; }"
        : "=r"(done) : "r"(mbar), "r"(parity) : "memory");
    if (!done) {
        asm volatile(
            "{ .reg .pred P1;\n"
            "WAIT_LOOP_%=:\n"
            " mbarrier.try_wait.parity.acquire.cta.shared::cta.b64 P1, [%0], %1, 0x989680;\n"
            " @P1 bra.uni WAIT_DONE_%=;\n"
            " bra.uni WAIT_LOOP_%=;\n"
            "WAIT_DONE_%=:\n}"
            :: "r"(mbar), "r"(parity) : "memory");
    }
}

__device__ __forceinline__ void ldsm_x4(uint32_t* r, uint32_t addr) {
    asm volatile("ldmatrix.sync.aligned.m8n8.x4.shared.b16 {%0,%1,%2,%3}, [%4];"
                 : "=r"(r[0]), "=r"(r[1]), "=r"(r[2]), "=r"(r[3]) : "r"(addr));
}
// fp16 mma, fp32 accumulate: k16 per instruction (2x tf32 k8 FLOP).
__device__ __forceinline__ void mma_f16(float* c, const uint32_t* a,
                                        uint32_t b0, uint32_t b1) {
    asm volatile(
        "mma.sync.aligned.m16n8k16.row.col.f32.f16.f16.f32 "
        "{%0,%1,%2,%3}, {%4,%5,%6,%7}, {%8,%9}, {%0,%1,%2,%3};"
        : "+f"(c[0]), "+f"(c[1]), "+f"(c[2]), "+f"(c[3])
        : "r"(a[0]), "r"(a[1]), "r"(a[2]), "r"(a[3]), "r"(b0), "r"(b1));
}

// ---------------------------------------------------------------------------
// Prep kernels: convert to fp16 (x) / sample+convert (W), sample bias.
// Each thread handles 8 elements -> one 16B half store.
// ---------------------------------------------------------------------------
__global__ void prep_x_kernel(const float4* __restrict__ x) {
    size_t i = (size_t)blockIdx.x * blockDim.x + threadIdx.x;
    float4 v0 = x[2 * i], v1 = x[2 * i + 1];
    __half2 h[4];
    h[0] = __floats2half2_rn(v0.x, v0.y);
    h[1] = __floats2half2_rn(v0.z, v0.w);
    h[2] = __floats2half2_rn(v1.x, v1.y);
    h[3] = __floats2half2_rn(v1.z, v1.w);
    reinterpret_cast<uint4*>(g_X)[i] = *reinterpret_cast<uint4*>(h);
}
__global__ void prep_w_kernel(const float4* __restrict__ mu,
                              const float4* __restrict__ ls,
                              const float4* __restrict__ eps) {
    size_t i = (size_t)blockIdx.x * blockDim.x + threadIdx.x;
    __half2 h[4];
    #pragma unroll
    for (int q = 0; q < 2; ++q) {
        float4 m = mu[2 * i + q], l = ls[2 * i + q], e = eps[2 * i + q];
        float4 w;
        w.x = m.x + expf(l.x) * e.x;
        w.y = m.y + expf(l.y) * e.y;
        w.z = m.z + expf(l.z) * e.z;
        w.w = m.w + expf(l.w) * e.w;
        h[2 * q + 0] = __floats2half2_rn(w.x, w.y);
        h[2 * q + 1] = __floats2half2_rn(w.z, w.w);
    }
    reinterpret_cast<uint4*>(g_W)[i] = *reinterpret_cast<uint4*>(h);
}
__global__ void prep_bias_kernel(const float* __restrict__ mub,
                                 const float* __restrict__ lsb,
                                 const float* __restrict__ epsb) {
    int i = blockIdx.x * blockDim.x + threadIdx.x;
    if (i < ODIM) g_B[i] = mub[i] + expf(lsb[i]) * epsb[i];
}

// ---------------------------------------------------------------------------
// GEMM: 1024 CTAs (32 m x 32 n, n fastest), 320 threads:
// warps 0-7 consumers (64x64 tiles in 4x2), warps 8-9 producers (A/B halves).
// ---------------------------------------------------------------------------
__global__ void __launch_bounds__(320, 1)
rand_linear_gemm_kernel(float* __restrict__ out) {
    extern __shared__ char smem[];
    const uint32_t sb = smem_u32(smem);
    const int tid = threadIdx.x;
    const int lane = tid & 31;
    const int wid = tid >> 5;

    const int m_tile = blockIdx.x >> 5;    // 32
    const int n_tile = blockIdx.x & 31;    // 32 (fast-varying: W stays L2-hot)
    const int m0 = m_tile * TILE_M;
    const int n0 = n_tile * TILE_N;

    #define FULL_BAR(s)  (sb + OFF_BAR + (s) * 16)
    #define EMPTY_BAR(s) (sb + OFF_BAR + (s) * 16 + 8)

    if (tid == 0) {
        #pragma unroll
        for (int s = 0; s < STAGES; ++s) {
            MBARRIER_INIT(FULL_BAR(s), 64u);    // 2 producer warps x 32 lanes
            MBARRIER_INIT(EMPTY_BAR(s), 256u);  // 8 consumer warps x 32 lanes
        }
    }
    __syncthreads();   // only CTA-wide sync

    if (wid >= 8) {
        // ------------- producer warps: each fills half of A and half of B ----
        const int ph = wid - 8;            // 0 or 1
        const int r0 = lane >> 3;          // 0..3
        const int tc = lane & 7;           // 16B chunk (8 halfs) in 128B row
        const __half* gA = g_X + (size_t)(m0 + ph * 128 + r0) * KDIM + tc * 8;
        const __half* gB = g_W + (size_t)(n0 + ph * 64 + r0) * KDIM + tc * 8;
        const uint32_t aOff = (uint32_t)(ph * 128) * 128u;
        const uint32_t bOff = (uint32_t)(ph * 64) * 128u;
        const uint32_t sw0 = (uint32_t)r0 * 128u + (uint32_t)((tc ^ (r0 & 7)) << 4);
        const uint32_t sw1 = (uint32_t)(r0 + 4) * 128u +
                             (uint32_t)((tc ^ ((r0 + 4) & 7)) << 4);

        int slot = 0, phase = 1;
        for (int it = 0; it < K_ITERS; ++it) {
            mbar_wait(EMPTY_BAR(slot), phase);
            const uint32_t aS = sb + slot * STAGE_BYTES + aOff;
            const uint32_t bS = sb + slot * STAGE_BYTES + A_BYTES + bOff;
            const __half* ga = gA + it * TILE_K;
            const __half* gb = gB + it * TILE_K;
            #pragma unroll
            for (int j = 0; j < 16; ++j) {   // A half: 128 rows
                cp16(aS + sw0 + j * 1024u, ga + (size_t)(8 * j) * KDIM);
                cp16(aS + sw1 + j * 1024u, ga + (size_t)(8 * j + 4) * KDIM);
            }
            #pragma unroll
            for (int j = 0; j < 8; ++j) {    // B half: 64 rows
                cp16(bS + sw0 + j * 1024u, gb + (size_t)(8 * j) * KDIM);
                cp16(bS + sw1 + j * 1024u, gb + (size_t)(8 * j + 4) * KDIM);
            }
            cp_async_arrive(FULL_BAR(slot));
            if (++slot == STAGES) { slot = 0; phase ^= 1; }
        }
        return;
    }

    // --------------------------- consumer warps ---------------------------
    const int wm0 = (wid & 3) * 64;        // 0..192
    const int wn0 = (wid >> 2) * 64;       // 0 or 64

    const int la15 = lane & 15;
    const uint32_t hi = (uint32_t)(lane >> 4);
    uint32_t aRow[4], aX7[4], bRow[4], bX7[4];
    #pragma unroll
    for (int i = 0; i < 4; ++i) {
        const uint32_t ra = (uint32_t)(wm0 + i * 16 + la15);
        aRow[i] = ra * 128u; aX7[i] = ra & 7u;
        const uint32_t rb = (uint32_t)(wn0 + i * 16 + la15);
        bRow[i] = rb * 128u; bX7[i] = rb & 7u;
    }

    float acc[4][8][4];
    #pragma unroll
    for (int i = 0; i < 4; ++i)
        #pragma unroll
        for (int j = 0; j < 8; ++j)
            #pragma unroll
            for (int r = 0; r < 4; ++r) acc[i][j][r] = 0.f;

    uint32_t a[2][4][4], b[2][4][4];

    // kk indexes a k16 step: 16B chunks 2*kk (k0-7) and 2*kk+1 (k8-15).
    // ldsm x4 with la15 rows + hi chunk gives exactly {a0,a1,a2,a3}; the
    // (lo,hi) reg pairs are exactly the m16n8k16 B frag {b0,b1}.
    #define LOAD_FRAGS(kk, buf, aB_, bB_)                                     \
        do {                                                                  \
            const uint32_t kc2 = (uint32_t)((kk) * 2) + hi;                   \
            _Pragma("unroll")                                                 \
            for (int i_ = 0; i_ < 4; ++i_)                                    \
                ldsm_x4(a[buf][i_], (aB_) + aRow[i_] + ((kc2 ^ aX7[i_]) << 4)); \
            _Pragma("unroll")                                                 \
            for (int j_ = 0; j_ < 4; ++j_)                                    \
                ldsm_x4(b[buf][j_], (bB_) + bRow[j_] + ((kc2 ^ bX7[j_]) << 4)); \
        } while (0)

    #define MMA_BLOCK(buf)                                                    \
        do {                                                                  \
            _Pragma("unroll")                                                 \
            for (int i_ = 0; i_ < 4; ++i_) {                                  \
                _Pragma("unroll")                                             \
                for (int j_ = 0; j_ < 4; ++j_) {                              \
                    mma_f16(acc[i_][2 * j_ + 0], a[buf][i_], b[buf][j_][0],   \
                            b[buf][j_][2]);                                   \
                    mma_f16(acc[i_][2 * j_ + 1], a[buf][i_], b[buf][j_][1],   \
                            b[buf][j_][3]);                                   \
                }                                                             \
            }                                                                 \
        } while (0)

    int slot = 0, phase = 0;
    for (int it = 0; it < K_ITERS; ++it) {
        mbar_wait(FULL_BAR(slot), phase);
        const uint32_t aB = sb + slot * STAGE_BYTES;
        const uint32_t bB = aB + A_BYTES;

        LOAD_FRAGS(0, 0, aB, bB);
        LOAD_FRAGS(1, 1, aB, bB);
        MMA_BLOCK(0);                      // k 0-15
        LOAD_FRAGS(2, 0, aB, bB);
        MMA_BLOCK(1);                      // k 16-31
        LOAD_FRAGS(3, 1, aB, bB);
        MBARRIER_ARRIVE(EMPTY_BAR(slot));  // stage reads done — release early
        MMA_BLOCK(0);                      // k 32-47
        MMA_BLOCK(1);                      // k 48-63

        if (++slot == STAGES) { slot = 0; phase ^= 1; }
    }

    // ---- epilogue: fused bias ----
    const int gid = lane >> 2;
    const int kc = lane & 3;
    #pragma unroll
    for (int j = 0; j < 8; ++j) {
        const int col = n0 + wn0 + j * 8 + kc * 2;
        float2 bv;
        bv.x = __ldg(&g_B[col]);
        bv.y = __ldg(&g_B[col + 1]);
        #pragma unroll
        for (int i = 0; i < 4; ++i) {
            const int row = m0 + wm0 + i * 16 + gid;
            float2 v0 = make_float2(acc[i][j][0] + bv.x, acc[i][j][1] + bv.y);
            float2 v1 = make_float2(acc[i][j][2] + bv.x, acc[i][j][3] + bv.y);
            *reinterpret_cast<float2*>(out + (size_t)row * ODIM + col) = v0;
            *reinterpret_cast<float2*>(out + (size_t)(row + 8) * ODIM + col) = v1;
        }
    }
}

// ---------------------------------------------------------------------------
extern "C" void kernel_launch(void* const* d_in, const int* in_sizes, int n_in,
                              void* d_out, int out_size) {
    const float* x    = (const float*)d_in[0];
    const float* muw  = (const float*)d_in[1];
    const float* lsw  = (const float*)d_in[2];
    const float* mub  = (const float*)d_in[3];
    const float* lsb  = (const float*)d_in[4];
    const float* epsw = (const float*)d_in[5];
    const float* epsb = (const float*)d_in[6];
    float* out = (float*)d_out;

    cudaFuncSetAttribute(rand_linear_gemm_kernel,
                         cudaFuncAttributeMaxDynamicSharedMemorySize, SMEM_TOTAL);

    // x: 33554432 elems / 8 per thread = 4194304 threads -> 16384 blocks
    prep_x_kernel<<<16384, 256>>>((const float4*)x);
    // W: 16777216 / 8 = 2097152 -> 8192 blocks
    prep_w_kernel<<<8192, 256>>>((const float4*)muw, (const float4*)lsw,
                                 (const float4*)epsw);
    prep_bias_kernel<<<16, 256>>>(mub, lsb, epsb);

    rand_linear_gemm_kernel<<<(NROWS / TILE_M) * (ODIM / TILE_N), 320,
                              SMEM_TOTAL>>>(out);
}